// round 14
// baseline (speedup 1.0000x reference)
#include <cuda_runtime.h>
#include <math.h>

typedef unsigned long long ull;

// ---------------- problem constants ----------------
#define NT       512     // 16 warps; four independent 128-thread groups
#define BT       16      // batch items per block -> 128 blocks
#define T_STEPS  128
#define STATE    115
#define ACT      39
#define CIN      154
#define COUT     116

#define SBUF 132
#define SA   44

// ---------------- shared memory layout (float offsets) ----------------
#define OW0   0          // padded [156][16]
#define OW1   2496
#define OW2   3008
#define OW3   5056
#define OW4   13248
#define OW5   21440
#define OW6   23488
#define OW7   24000
#define OW8   24128      // padded [8][120]
#define OWR   25088      // 348
#define OB0   25436
#define OB1   25452
#define OB2   25484
#define OB3   25548
#define OB4   25676
#define OB5   25740
#define OB6   25772
#define OB7   25788
#define OB8   25796      // 120 padded
#define OBR   25916
#define OBUFA 25920      // 16*132
#define OBUFB 28032      // 16*132
#define OXS   30144      // 16*132 (cols >=115 zero)
#define OAB0  32256      // 16*44 (cols >=39 zero)
#define OAB1  32960      // 16*44
#define OSCR  33664      // 1024 floats (256 per group)
#define SMEM_FLOATS 34688
#define SMEM_BYTES  (SMEM_FLOATS * 4)   // 138752 B -> 1 CTA/SM

#define GBAR() asm volatile("bar.sync %0, 128;" :: "r"(grp + 1) : "memory")

struct Params {
    const float* u;
    const float* W[9];
    const float* b[9];
    const float* Wr;
    const float* br;
    float* out;
};

// ---- packed f32x2 helpers ----
__device__ __forceinline__ ull pk2(float x, float y) {
    ull r; asm("mov.b64 %0, {%1, %2};" : "=l"(r) : "f"(x), "f"(y)); return r;
}
__device__ __forceinline__ void upk2(ull v, float& x, float& y) {
    asm("mov.b64 {%0, %1}, %2;" : "=f"(x), "=f"(y) : "l"(v));
}
__device__ __forceinline__ ull fma2(ull a, ull b, ull c) {
    ull d; asm("fma.rn.f32x2 %0, %1, %2, %3;" : "=l"(d) : "l"(a), "l"(b), "l"(c)); return d;
}
__device__ __forceinline__ ull addf2(ull a, ull b) {
    ull d; asm("add.rn.f32x2 %0, %1, %2;" : "=l"(d) : "l"(a), "l"(b)); return d;
}

__device__ __forceinline__ void cpy_sh(float* dst, const float* __restrict__ src, int n) {
    for (int k = threadIdx.x; k < n; k += NT) dst[k] = src[k];
}

__device__ __forceinline__ float elem4(const float4& v, int e) {
    return e == 0 ? v.x : e == 1 ? v.y : e == 2 ? v.z : v.w;
}

// ============ per-group layers: og = gtid>>2, it = gtid&3 (TB=1) ============
// Weight loads are shared by the 4 lanes of an og-quad (broadcast).

// TO=1 scalar layer
template<int FI, int FO, int WS, bool CLIP>
__device__ __forceinline__ void layerS1(const float* __restrict__ W,
                                        const float* __restrict__ bias,
                                        const float* __restrict__ in,
                                        float* __restrict__ out, int gtid) {
    const int og = gtid >> 2;
    const int it = gtid & 3;
    if (FO >= 32 || og < FO) {
        const float* inp = in + it * SBUF;
        float acc = bias[og];
#pragma unroll
        for (int i4 = 0; i4 < FI / 4; ++i4) {
            float4 av = *(const float4*)(inp + 4 * i4);
            acc = fmaf(av.x, W[(4 * i4 + 0) * WS + og], acc);
            acc = fmaf(av.y, W[(4 * i4 + 1) * WS + og], acc);
            acc = fmaf(av.z, W[(4 * i4 + 2) * WS + og], acc);
            acc = fmaf(av.w, W[(4 * i4 + 3) * WS + og], acc);
        }
        if constexpr (CLIP) acc = fminf(fmaxf(acc, 0.0f), 6.0f);
        out[it * SBUF + og] = acc;
    }
}

// TO=2 layer
template<int FI, int FO, int WS, bool CLIP>
__device__ __forceinline__ void layerV2(const float* __restrict__ W,
                                        const float* __restrict__ bias,
                                        const float* __restrict__ in,
                                        float* __restrict__ out, int gtid) {
    constexpr int OG = FO / 2;
    const int og = gtid >> 2;
    const int it = gtid & 3;
    if (OG >= 32 || og < OG) {
        const int o0 = og * 2;
        const float* inp = in + it * SBUF;
        float2 bv = *(const float2*)(bias + o0);
        ull acc = pk2(bv.x, bv.y);
#pragma unroll
        for (int i4 = 0; i4 < FI / 4; ++i4) {
            float4 av = *(const float4*)(inp + 4 * i4);
#pragma unroll
            for (int e = 0; e < 4; ++e) {
                float a = elem4(av, e);
                acc = fma2(pk2(a, a), *(const ull*)(W + (4 * i4 + e) * WS + o0), acc);
            }
        }
        float r0, r1; upk2(acc, r0, r1);
        if constexpr (CLIP) {
            r0 = fminf(fmaxf(r0, 0.0f), 6.0f);
            r1 = fminf(fmaxf(r1, 0.0f), 6.0f);
        }
        *(float2*)(out + it * SBUF + o0) = make_float2(r0, r1);
    }
}

// TO=4 layer (optional residual)
template<int FI, int FO, int WS, bool CLIP, bool RESID>
__device__ __forceinline__ void layerV4(const float* __restrict__ W,
                                        const float* __restrict__ bias,
                                        const float* __restrict__ in,
                                        float* __restrict__ out, int gtid) {
    constexpr int OG = FO / 4;
    const int og = gtid >> 2;
    const int it = gtid & 3;
    if (OG >= 32 || og < OG) {
        const int o0 = og * 4;
        const float* inp = in + it * SBUF;
        float4 bv = *(const float4*)(bias + o0);
        ull a0 = pk2(bv.x, bv.y), a1 = pk2(bv.z, bv.w);
#pragma unroll
        for (int i4 = 0; i4 < FI / 4; ++i4) {
            float4 av = *(const float4*)(inp + 4 * i4);
#pragma unroll
            for (int e = 0; e < 4; ++e) {
                float a = elem4(av, e);
                ull x = pk2(a, a);
                ulonglong2 w = *(const ulonglong2*)(W + (4 * i4 + e) * WS + o0);
                a0 = fma2(x, w.x, a0);
                a1 = fma2(x, w.y, a1);
            }
        }
        float r0, r1, r2, r3;
        upk2(a0, r0, r1); upk2(a1, r2, r3);
        if constexpr (CLIP) {
            r0 = fminf(fmaxf(r0, 0.0f), 6.0f);
            r1 = fminf(fmaxf(r1, 0.0f), 6.0f);
            r2 = fminf(fmaxf(r2, 0.0f), 6.0f);
            r3 = fminf(fmaxf(r3, 0.0f), 6.0f);
        }
        float* op = out + it * SBUF + o0;
        if constexpr (RESID) {
            float4 xv = *(const float4*)op;
            xv.x += r0; xv.y += r1; xv.z += r2; xv.w += r3;
            *(float4*)op = xv;
        } else {
            *(float4*)op = make_float4(r0, r1, r2, r3);
        }
    }
}

// L0 quarter: NF4 float4 rows, one item, og-pair
template<int NF4>
__device__ __forceinline__ void l0_part1(const float* __restrict__ s,
                                         const float* __restrict__ W,
                                         ull& acc) {
#pragma unroll
    for (int i4 = 0; i4 < NF4; ++i4) {
        float4 v = *(const float4*)(s + 4 * i4);
#pragma unroll
        for (int e = 0; e < 4; ++e) {
            float a = elem4(v, e);
            acc = fma2(pk2(a, a), *(const ull*)(W + (4 * i4 + e) * 16), acc);
        }
    }
}

// reward: 32 lanes per item (4 items per group)
__device__ __forceinline__ void reward32(const float* __restrict__ sh,
                                         float* __restrict__ out,
                                         int b0, int itemBase, int gtid, int t) {
    const int it = itemBase + (gtid >> 5);
    const int l = gtid & 31;
    float p0 = 0.f, p1 = 0.f, p2 = 0.f;
    const float* xr = sh + OXS + it * SBUF;
    const float* Wr = sh + OWR;
#pragma unroll
    for (int i = l; i < STATE; i += 32) {
        float v = xr[i];
        p0 = fmaf(v, Wr[3 * i + 0], p0);
        p1 = fmaf(v, Wr[3 * i + 1], p1);
        p2 = fmaf(v, Wr[3 * i + 2], p2);
    }
#pragma unroll
    for (int off = 16; off > 0; off >>= 1) {
        p0 += __shfl_down_sync(0xffffffffu, p0, off);
        p1 += __shfl_down_sync(0xffffffffu, p1, off);
        p2 += __shfl_down_sync(0xffffffffu, p2, off);
    }
    if (l == 0) {
        p0 += sh[OBR + 0]; p1 += sh[OBR + 1]; p2 += sh[OBR + 2];
        out[((size_t)(b0 + it) * T_STEPS + t) * COUT + STATE] =
            -sqrtf(p0 * p0 + p1 * p1 + p2 * p2);
    }
}

__global__ void __launch_bounds__(NT, 1) worldnet_kernel(Params p) {
    extern __shared__ float sh[];
    const int tid = threadIdx.x;
    const int grp = tid >> 7;            // 0..3
    const int gtid = tid & 127;
    const int b0 = blockIdx.x * BT;
    const int itemBase = grp * 4;

    // ---- one-time weight/bias staging ----
    for (int k = tid; k < 156 * 16; k += NT) {
        int r = k >> 4, c = k & 15;
        float v = 0.0f;
        if (r < 115)                  v = p.W[0][r * 16 + c];
        else if (r >= 116 && r < 155) v = p.W[0][(r - 1) * 16 + c];
        sh[OW0 + k] = v;
    }
    cpy_sh(sh + OW1, p.W[1], 16 * 32);
    cpy_sh(sh + OW2, p.W[2], 32 * 64);
    cpy_sh(sh + OW3, p.W[3], 64 * 128);
    cpy_sh(sh + OW4, p.W[4], 128 * 64);
    cpy_sh(sh + OW5, p.W[5], 64 * 32);
    cpy_sh(sh + OW6, p.W[6], 32 * 16);
    cpy_sh(sh + OW7, p.W[7], 16 * 8);
    for (int k = tid; k < 8 * 120; k += NT) {
        int i = k / 120, o = k - i * 120;
        sh[OW8 + k] = (o < STATE) ? p.W[8][i * STATE + o] : 0.0f;
    }
    for (int k = tid; k < 348; k += NT)
        sh[OWR + k] = (k < STATE * 3) ? p.Wr[k] : 0.0f;
    cpy_sh(sh + OB0, p.b[0], 16);
    cpy_sh(sh + OB1, p.b[1], 32);
    cpy_sh(sh + OB2, p.b[2], 64);
    cpy_sh(sh + OB3, p.b[3], 128);
    cpy_sh(sh + OB4, p.b[4], 64);
    cpy_sh(sh + OB5, p.b[5], 32);
    cpy_sh(sh + OB6, p.b[6], 16);
    cpy_sh(sh + OB7, p.b[7], 8);
    for (int k = tid; k < 120; k += NT)
        sh[OB8 + k] = (k < STATE) ? p.b[8][k] : 0.0f;
    for (int k = tid; k < 4; k += NT)
        sh[OBR + k] = (k < 3) ? p.br[k] : 0.0f;

    // ---- init XS (cols >= 115 zero) ----
    for (int k = tid; k < BT * SBUF; k += NT) {
        int b = k / SBUF, i = k - b * SBUF;
        sh[OXS + k] = (i < STATE)
            ? p.u[(size_t)(b0 + b) * T_STEPS * CIN + i] : 0.0f;
    }
    // actions for t=0 into OAB0; zero pad cols of both buffers
    for (int k = tid; k < BT * ACT; k += NT) {
        int b = k / ACT, j = k - b * ACT;
        sh[OAB0 + b * SA + j] = p.u[(size_t)(b0 + b) * T_STEPS * CIN + STATE + j];
    }
    if (tid < 2 * BT) {
        int buf = tid >> 4, b = tid & 15;
        float* ab = sh + (buf ? OAB1 : OAB0) + b * SA;
#pragma unroll
        for (int j = ACT; j < SA; ++j) ab[j] = 0.0f;
    }
    __syncthreads();
    // from here the four groups never share a barrier

    const float* bufAG = sh + OBUFA + itemBase * SBUF;
    float* bufAGw = sh + OBUFA + itemBase * SBUF;
    const float* bufBG = sh + OBUFB + itemBase * SBUF;
    float* bufBGw = sh + OBUFB + itemBase * SBUF;
    float* xsGw   = sh + OXS   + itemBase * SBUF;
    float* scrG   = sh + OSCR  + grp * 256;

    // ---- time loop (group-independent) ----
    for (int t = 0; t < T_STEPS; ++t) {
        if (t > 0) reward32(sh, p.out, b0, itemBase, gtid, t - 1);
        // out[:, t, 0:116] = x_t : 4 items x 29 float4
        {
            const int it = itemBase + (gtid >> 5);
            const int c = gtid & 31;
            if (c < 29) {
                float4 v = *(const float4*)(sh + OXS + it * SBUF + 4 * c);
                *(float4*)(p.out + ((size_t)(b0 + it) * T_STEPS + t) * COUT + 4 * c) = v;
            }
        }
        // prefetch actions for t+1
        if (t < T_STEPS - 1) {
            const int it = itemBase + (gtid >> 5);
            float* ab = sh + (((t + 1) & 1) ? OAB1 : OAB0) + it * SA;
            const float* us = p.u + ((size_t)(b0 + it) * T_STEPS + t + 1) * CIN + STATE;
            for (int j = gtid & 31; j < ACT; j += 32) ab[j] = us[j];
        }

        // ---- L0: q(4) x pg(8) x it(4) = 128 threads, one quarter each ----
        {
            const int q  = gtid >> 5;
            const int pg = (gtid >> 2) & 7;
            const int it4 = gtid & 3;
            const int o0 = pg * 2;
            ull acc;
            if (q == 0) {
                float2 bv = *(const float2*)(sh + OB0 + o0);
                acc = pk2(bv.x, bv.y);
            } else acc = 0ull;
            const int i0 = itemBase + it4;
            const float* xr = sh + OXS + i0 * SBUF;
            const float* ab = sh + ((t & 1) ? OAB1 : OAB0) + i0 * SA;
            if (q == 0)      l0_part1<10>(xr,      sh + OW0 + o0,           acc);
            else if (q == 1) l0_part1<10>(xr + 40, sh + OW0 + 40 * 16 + o0, acc);
            else if (q == 2) l0_part1< 9>(xr + 80, sh + OW0 + 80 * 16 + o0, acc);
            else             l0_part1<10>(ab,      sh + OW0 + 116 * 16 + o0, acc);
            *(ull*)(scrG + ((it4 * 8 + pg) * 4 + q) * 2) = acc;
        }
        GBAR();
        if (gtid < 32) {   // combine quarters -> BUFB
            const int it4 = gtid >> 3;
            const int pg = gtid & 7;
            const float* base = scrG + (it4 * 8 + pg) * 8;
            ulonglong2 v01 = *(const ulonglong2*)(base);
            ulonglong2 v23 = *(const ulonglong2*)(base + 4);
            float a0, a1, c0, c1, d0, d1, e0, e1;
            upk2(v01.x, a0, a1); upk2(v01.y, c0, c1);
            upk2(v23.x, d0, d1); upk2(v23.y, e0, e1);
            float lo = (a0 + c0) + (d0 + e0);
            float hi = (a1 + c1) + (d1 + e1);
            lo = fminf(fmaxf(lo, 0.0f), 6.0f);
            hi = fminf(fmaxf(hi, 0.0f), 6.0f);
            *(float2*)(bufBGw + it4 * SBUF + pg * 2) = make_float2(lo, hi);
        }
        GBAR();

        layerS1< 16,  32,  32, true>(sh + OW1, sh + OB1, bufBG, bufAGw, gtid); GBAR();
        layerV2< 32,  64,  64, true>(sh + OW2, sh + OB2, bufAG, bufBGw, gtid); GBAR();
        layerV4< 64, 128, 128, true, false>(sh + OW3, sh + OB3, bufBG, bufAGw, gtid); GBAR();

        // ---- L4: 128->64, TO=4, K halves: kh(2) x og(16) x it(4) = 128 thr ----
        {
            const int kh = gtid >> 6;
            const int og = (gtid >> 2) & 15;
            const int it = gtid & 3;
            const int o0 = og * 4;
            const int rb = kh * 64;
            ull a0, a1;
            if (kh == 0) {
                float4 bv = *(const float4*)(sh + OB4 + o0);
                a0 = pk2(bv.x, bv.y); a1 = pk2(bv.z, bv.w);
            } else { a0 = 0ull; a1 = 0ull; }
            const float* inp = bufAG + it * SBUF + rb;
#pragma unroll
            for (int i4 = 0; i4 < 16; ++i4) {
                float4 av = *(const float4*)(inp + 4 * i4);
#pragma unroll
                for (int e = 0; e < 4; ++e) {
                    float a = elem4(av, e);
                    ull x = pk2(a, a);
                    ulonglong2 w = *(const ulonglong2*)(sh + OW4 + (rb + 4 * i4 + e) * 64 + o0);
                    a0 = fma2(x, w.x, a0);
                    a1 = fma2(x, w.y, a1);
                }
            }
            if (kh == 1) {
                float* s = scrG + (gtid & 63) * 4;
                *(ull*)(s)     = a0;
                *(ull*)(s + 2) = a1;
            }
            GBAR();
            if (kh == 0) {
                const float* s = scrG + gtid * 4;
                ull f0 = addf2(a0, *(const ull*)(s));
                ull f1 = addf2(a1, *(const ull*)(s + 2));
                float r0, r1, r2, r3;
                upk2(f0, r0, r1); upk2(f1, r2, r3);
                r0 = fminf(fmaxf(r0, 0.0f), 6.0f);
                r1 = fminf(fmaxf(r1, 0.0f), 6.0f);
                r2 = fminf(fmaxf(r2, 0.0f), 6.0f);
                r3 = fminf(fmaxf(r3, 0.0f), 6.0f);
                *(float4*)(bufBGw + it * SBUF + o0) = make_float4(r0, r1, r2, r3);
            }
            GBAR();
        }

        layerS1< 64,  32,  32, true>(sh + OW5, sh + OB5, bufBG, bufAGw, gtid); GBAR();
        layerS1< 32,  16,  16, true>(sh + OW6, sh + OB6, bufAG, bufBGw, gtid); GBAR();
        layerS1< 16,   8,   8, true>(sh + OW7, sh + OB7, bufBG, bufAGw, gtid); GBAR();
        layerV4<  8, 120, 120, false, true>(sh + OW8, sh + OB8, bufAG, xsGw, gtid); GBAR();
    }
    reward32(sh, p.out, b0, itemBase, gtid, T_STEPS - 1);
}

extern "C" void kernel_launch(void* const* d_in, const int* in_sizes, int n_in,
                              void* d_out, int out_size) {
    Params p;
    p.u = (const float*)d_in[0];
    for (int i = 0; i < 9; ++i) {
        p.W[i] = (const float*)d_in[1 + 2 * i];
        p.b[i] = (const float*)d_in[2 + 2 * i];
    }
    p.Wr = (const float*)d_in[19];
    p.br = (const float*)d_in[20];
    p.out = (float*)d_out;

    cudaFuncSetAttribute(worldnet_kernel,
                         cudaFuncAttributeMaxDynamicSharedMemorySize, SMEM_BYTES);
    worldnet_kernel<<<2048 / BT, NT, SMEM_BYTES>>>(p);
}

// round 15
// speedup vs baseline: 1.1347x; 1.1347x over previous
#include <cuda_runtime.h>
#include <math.h>

typedef unsigned long long ull;

// ---------------- problem constants ----------------
#define NT       256     // 8 warps; two independent 128-thread groups
#define BT       16      // batch items per block -> 128 blocks
#define T_STEPS  128
#define STATE    115
#define ACT      39
#define CIN      154
#define COUT     116

#define SBUF 132
#define SA   44

// ---------------- shared memory layout (float offsets) ----------------
#define OW0   0          // padded [156][16]
#define OW1   2496
#define OW2   3008
#define OW3   5056
#define OW4   13248
#define OW5   21440
#define OW6   23488
#define OW7   24000
#define OW8   24128      // padded [8][120]
#define OWR   25088      // 348
#define OB0   25436
#define OB1   25452
#define OB2   25484
#define OB3   25548
#define OB4   25676
#define OB5   25740
#define OB6   25772
#define OB7   25788
#define OB8   25796      // 120 padded
#define OBR   25916
#define OBUFA 25920      // 16*132
#define OBUFB 28032      // 16*132
#define OXS   30144      // 16*132 (cols >=115 zero)
#define OAB0  32256      // 16*44 (cols >=39 zero)
#define OAB1  32960      // 16*44
#define OSCR  33664      // 1024 floats
#define SMEM_FLOATS 34688
#define SMEM_BYTES  (SMEM_FLOATS * 4)   // 138752 B -> 1 CTA/SM

#define GBAR() asm volatile("bar.sync %0, 128;" :: "r"(grp + 1) : "memory")

struct Params {
    const float* u;
    const float* W[9];
    const float* b[9];
    const float* Wr;
    const float* br;
    float* out;
};

// ---- packed f32x2 helpers ----
__device__ __forceinline__ ull pk2(float x, float y) {
    ull r; asm("mov.b64 %0, {%1, %2};" : "=l"(r) : "f"(x), "f"(y)); return r;
}
__device__ __forceinline__ void upk2(ull v, float& x, float& y) {
    asm("mov.b64 {%0, %1}, %2;" : "=f"(x), "=f"(y) : "l"(v));
}
__device__ __forceinline__ ull fma2(ull a, ull b, ull c) {
    ull d; asm("fma.rn.f32x2 %0, %1, %2, %3;" : "=l"(d) : "l"(a), "l"(b), "l"(c)); return d;
}
__device__ __forceinline__ ull addf2(ull a, ull b) {
    ull d; asm("add.rn.f32x2 %0, %1, %2;" : "=l"(d) : "l"(a), "l"(b)); return d;
}

__device__ __forceinline__ void cpy_sh(float* dst, const float* __restrict__ src, int n) {
    for (int k = threadIdx.x; k < n; k += NT) dst[k] = src[k];
}

__device__ __forceinline__ float elem4(const float4& v, int e) {
    return e == 0 ? v.x : e == 1 ? v.y : e == 2 ? v.z : v.w;
}

// ---- TB=2 layer inside one group, with even/odd accumulator split.
// og = gtid>>2 (32 slots), bp = gtid&3; thread handles items (bp, bp+4).
template<int FI, int FO, int TO, int WS, bool CLIP, bool RESID>
__device__ __forceinline__ void layerN(const float* __restrict__ W,
                                       const float* __restrict__ bias,
                                       const float* __restrict__ in,
                                       float* __restrict__ out,
                                       int og, int bp) {
    constexpr int OG = FO / TO;
    static_assert((FI / 4) % 2 == 0, "even i4 count required");
    if (og < OG) {
        const int o0 = og * TO;
        const float* i0 = in + bp * SBUF;
        const float* i1 = in + (bp + 4) * SBUF;
        // even-parity accumulators carry the bias; odd start at 0
        ull aA0, aB0, aA1, aB1;           // even
        ull oA0 = 0, oB0 = 0, oA1 = 0, oB1 = 0;  // odd
        if constexpr (TO == 2) {
            float2 bv = *(const float2*)(bias + o0);
            aA0 = pk2(bv.x, bv.y); aA1 = aA0;
            aB0 = 0; aB1 = 0;
        } else {
            float4 bv = *(const float4*)(bias + o0);
            aA0 = pk2(bv.x, bv.y); aB0 = pk2(bv.z, bv.w);
            aA1 = aA0;             aB1 = aB0;
        }
#pragma unroll
        for (int i8 = 0; i8 < FI / 8; ++i8) {
#pragma unroll
            for (int par = 0; par < 2; ++par) {
                const int i4 = 2 * i8 + par;
                float4 v0 = *(const float4*)(i0 + 4 * i4);
                float4 v1 = *(const float4*)(i1 + 4 * i4);
#pragma unroll
                for (int e = 0; e < 4; ++e) {
                    const int i = 4 * i4 + e;
                    float e0 = elem4(v0, e);
                    float e1 = elem4(v1, e);
                    ull x0 = pk2(e0, e0);
                    ull x1 = pk2(e1, e1);
                    if constexpr (TO == 2) {
                        ull w = *(const ull*)(W + i * WS + o0);
                        if (par == 0) {
                            aA0 = fma2(x0, w, aA0);
                            aA1 = fma2(x1, w, aA1);
                        } else {
                            oA0 = fma2(x0, w, oA0);
                            oA1 = fma2(x1, w, oA1);
                        }
                    } else {
                        ulonglong2 w = *(const ulonglong2*)(W + i * WS + o0);
                        if (par == 0) {
                            aA0 = fma2(x0, w.x, aA0); aB0 = fma2(x0, w.y, aB0);
                            aA1 = fma2(x1, w.x, aA1); aB1 = fma2(x1, w.y, aB1);
                        } else {
                            oA0 = fma2(x0, w.x, oA0); oB0 = fma2(x0, w.y, oB0);
                            oA1 = fma2(x1, w.x, oA1); oB1 = fma2(x1, w.y, oB1);
                        }
                    }
                }
            }
        }
        // merge parities
        aA0 = addf2(aA0, oA0); aA1 = addf2(aA1, oA1);
        if constexpr (TO == 4) {
            aB0 = addf2(aB0, oB0); aB1 = addf2(aB1, oB1);
        }
#pragma unroll
        for (int it = 0; it < 2; ++it) {
            float* op = out + (bp + 4 * it) * SBUF + o0;
            ull pa = it ? aA1 : aA0;
            if constexpr (TO == 2) {
                float r0, r1; upk2(pa, r0, r1);
                if constexpr (CLIP) {
                    r0 = fminf(fmaxf(r0, 0.0f), 6.0f);
                    r1 = fminf(fmaxf(r1, 0.0f), 6.0f);
                }
                *(float2*)op = make_float2(r0, r1);
            } else {
                ull pb = it ? aB1 : aB0;
                float r0, r1, r2, r3;
                upk2(pa, r0, r1); upk2(pb, r2, r3);
                if constexpr (CLIP) {
                    r0 = fminf(fmaxf(r0, 0.0f), 6.0f);
                    r1 = fminf(fmaxf(r1, 0.0f), 6.0f);
                    r2 = fminf(fmaxf(r2, 0.0f), 6.0f);
                    r3 = fminf(fmaxf(r3, 0.0f), 6.0f);
                }
                if constexpr (RESID) {
                    float4 xv = *(const float4*)op;
                    xv.x += r0; xv.y += r1; xv.z += r2; xv.w += r3;
                    *(float4*)op = xv;
                } else {
                    *(float4*)op = make_float4(r0, r1, r2, r3);
                }
            }
        }
    }
}

// ---- L0 partial with even/odd split: NF4 float4 rows for two items ----
template<int NF4>
__device__ __forceinline__ void l0_part2(const float* __restrict__ s0,
                                         const float* __restrict__ s1,
                                         const float* __restrict__ W,
                                         ull& a0, ull& a1) {
    ull o0 = 0, o1 = 0;
#pragma unroll
    for (int i4 = 0; i4 < NF4; ++i4) {
        float4 v0 = *(const float4*)(s0 + 4 * i4);
        float4 v1 = *(const float4*)(s1 + 4 * i4);
#pragma unroll
        for (int e = 0; e < 4; ++e) {
            ull w = *(const ull*)(W + (4 * i4 + e) * 16);
            float e0 = elem4(v0, e), e1 = elem4(v1, e);
            if (i4 & 1) {
                o0 = fma2(pk2(e0, e0), w, o0);
                o1 = fma2(pk2(e1, e1), w, o1);
            } else {
                a0 = fma2(pk2(e0, e0), w, a0);
                a1 = fma2(pk2(e1, e1), w, a1);
            }
        }
    }
    a0 = addf2(a0, o0);
    a1 = addf2(a1, o1);
}

// reward for x stored in XS (= x_{t+1} after L8): 16 lanes/item
__device__ __forceinline__ void reward16(const float* __restrict__ sh,
                                         float* __restrict__ out,
                                         int b0, int itemBase, int gtid, int t) {
    const int it = itemBase + (gtid >> 4);
    const int l = gtid & 15;
    float p0 = 0.f, p1 = 0.f, p2 = 0.f;
    const float* xr = sh + OXS + it * SBUF;
    const float* Wr = sh + OWR;
#pragma unroll
    for (int i = l; i < STATE; i += 16) {
        float v = xr[i];
        p0 = fmaf(v, Wr[3 * i + 0], p0);
        p1 = fmaf(v, Wr[3 * i + 1], p1);
        p2 = fmaf(v, Wr[3 * i + 2], p2);
    }
#pragma unroll
    for (int off = 8; off > 0; off >>= 1) {
        p0 += __shfl_down_sync(0xffffffffu, p0, off, 16);
        p1 += __shfl_down_sync(0xffffffffu, p1, off, 16);
        p2 += __shfl_down_sync(0xffffffffu, p2, off, 16);
    }
    if (l == 0) {
        p0 += sh[OBR + 0]; p1 += sh[OBR + 1]; p2 += sh[OBR + 2];
        out[((size_t)(b0 + it) * T_STEPS + t) * COUT + STATE] =
            -sqrtf(p0 * p0 + p1 * p1 + p2 * p2);
    }
}

__global__ void __launch_bounds__(NT, 1) worldnet_kernel(Params p) {
    extern __shared__ float sh[];
    const int tid = threadIdx.x;
    const int grp = tid >> 7;       // 0 or 1
    const int gtid = tid & 127;
    const int og = gtid >> 2;       // 0..31
    const int bp = gtid & 3;        // 0..3
    const int b0 = blockIdx.x * BT;
    const int itemBase = grp * 8;

    // ---- one-time weight/bias staging (all 256 threads) ----
    for (int k = tid; k < 156 * 16; k += NT) {
        int r = k >> 4, c = k & 15;
        float v = 0.0f;
        if (r < 115)                  v = p.W[0][r * 16 + c];
        else if (r >= 116 && r < 155) v = p.W[0][(r - 1) * 16 + c];
        sh[OW0 + k] = v;
    }
    cpy_sh(sh + OW1, p.W[1], 16 * 32);
    cpy_sh(sh + OW2, p.W[2], 32 * 64);
    cpy_sh(sh + OW3, p.W[3], 64 * 128);
    cpy_sh(sh + OW4, p.W[4], 128 * 64);
    cpy_sh(sh + OW5, p.W[5], 64 * 32);
    cpy_sh(sh + OW6, p.W[6], 32 * 16);
    cpy_sh(sh + OW7, p.W[7], 16 * 8);
    for (int k = tid; k < 8 * 120; k += NT) {
        int i = k / 120, o = k - i * 120;
        sh[OW8 + k] = (o < STATE) ? p.W[8][i * STATE + o] : 0.0f;
    }
    for (int k = tid; k < 348; k += NT)
        sh[OWR + k] = (k < STATE * 3) ? p.Wr[k] : 0.0f;
    cpy_sh(sh + OB0, p.b[0], 16);
    cpy_sh(sh + OB1, p.b[1], 32);
    cpy_sh(sh + OB2, p.b[2], 64);
    cpy_sh(sh + OB3, p.b[3], 128);
    cpy_sh(sh + OB4, p.b[4], 64);
    cpy_sh(sh + OB5, p.b[5], 32);
    cpy_sh(sh + OB6, p.b[6], 16);
    cpy_sh(sh + OB7, p.b[7], 8);
    for (int k = tid; k < 120; k += NT)
        sh[OB8 + k] = (k < STATE) ? p.b[8][k] : 0.0f;
    for (int k = tid; k < 4; k += NT)
        sh[OBR + k] = (k < 3) ? p.br[k] : 0.0f;

    // ---- init XS (cols >= 115 zero) ----
    for (int k = tid; k < BT * SBUF; k += NT) {
        int b = k / SBUF, i = k - b * SBUF;
        sh[OXS + k] = (i < STATE)
            ? p.u[(size_t)(b0 + b) * T_STEPS * CIN + i] : 0.0f;
    }
    // actions for t=0 into OAB0; zero pad cols of both buffers
    for (int k = tid; k < BT * ACT; k += NT) {
        int b = k / ACT, j = k - b * ACT;
        sh[OAB0 + b * SA + j] = p.u[(size_t)(b0 + b) * T_STEPS * CIN + STATE + j];
    }
    if (tid < 2 * BT) {
        int buf = tid >> 4, b = tid & 15;
        float* ab = sh + (buf ? OAB1 : OAB0) + b * SA;
#pragma unroll
        for (int j = ACT; j < SA; ++j) ab[j] = 0.0f;
    }
    __syncthreads();
    // after this point the two groups never share a barrier

    const float* bufAG = sh + OBUFA + itemBase * SBUF;
    float* bufAGw = sh + OBUFA + itemBase * SBUF;
    float* bufBGw = sh + OBUFB + itemBase * SBUF;
    float* xsGw   = sh + OXS   + itemBase * SBUF;

    // ---- time loop (group-independent) ----
    for (int t = 0; t < T_STEPS; ++t) {
        if (t > 0) reward16(sh, p.out, b0, itemBase, gtid, t - 1);
        // out[:, t, 0:116] = x_t
        {
            const int it = itemBase + (gtid >> 4);
            for (int c = gtid & 15; c < 29; c += 16) {
                float4 v = *(const float4*)(sh + OXS + it * SBUF + 4 * c);
                *(float4*)(p.out + ((size_t)(b0 + it) * T_STEPS + t) * COUT + 4 * c) = v;
            }
        }
        // prefetch actions for t+1 into the other buffer
        if (t < T_STEPS - 1) {
            const int it = itemBase + (gtid >> 4);
            float* ab = sh + (((t + 1) & 1) ? OAB1 : OAB0) + it * SA;
            const float* us = p.u + ((size_t)(b0 + it) * T_STEPS + t + 1) * CIN + STATE;
            for (int j = gtid & 15; j < ACT; j += 16) ab[j] = us[j];
        }
        // ---- L0 partial: 8 output-pairs x 4 K-quarters ----
        {
            const int pg = og & 7;
            const int q  = og >> 3;
            const int o0 = pg * 2;
            ull a0, a1;
            if (q == 0) {
                float2 bv = *(const float2*)(sh + OB0 + o0);
                a0 = pk2(bv.x, bv.y); a1 = a0;
            } else { a0 = 0ull; a1 = 0ull; }
            const int i0 = itemBase + bp, i1 = i0 + 4;
            const float* x0 = sh + OXS + i0 * SBUF;
            const float* x1 = sh + OXS + i1 * SBUF;
            const float* abase = sh + ((t & 1) ? OAB1 : OAB0);
            if (q == 0)      l0_part2<10>(x0,      x1,      sh + OW0 + o0,           a0, a1);
            else if (q == 1) l0_part2<10>(x0 + 40, x1 + 40, sh + OW0 + 40 * 16 + o0, a0, a1);
            else if (q == 2) l0_part2< 9>(x0 + 80, x1 + 80, sh + OW0 + 80 * 16 + o0, a0, a1);
            else             l0_part2<10>(abase + i0 * SA, abase + i1 * SA,
                                          sh + OW0 + 116 * 16 + o0, a0, a1);
            *(ull*)(sh + OSCR + (i0 * 8 + pg) * 8 + q * 2) = a0;
            *(ull*)(sh + OSCR + (i1 * 8 + pg) * 8 + q * 2) = a1;
        }
        GBAR();
        if (gtid < 64) {   // combine quarters -> OBUFB
            const int pg = gtid & 7;
            const int it = itemBase + (gtid >> 3);
            const float* base = sh + OSCR + (it * 8 + pg) * 8;
            ulonglong2 v01 = *(const ulonglong2*)(base);
            ulonglong2 v23 = *(const ulonglong2*)(base + 4);
            float a0, a1, c0, c1, d0, d1, e0, e1;
            upk2(v01.x, a0, a1); upk2(v01.y, c0, c1);
            upk2(v23.x, d0, d1); upk2(v23.y, e0, e1);
            float lo = (a0 + c0) + (d0 + e0);
            float hi = (a1 + c1) + (d1 + e1);
            lo = fminf(fmaxf(lo, 0.0f), 6.0f);
            hi = fminf(fmaxf(hi, 0.0f), 6.0f);
            *(float2*)(sh + OBUFB + it * SBUF + pg * 2) = make_float2(lo, hi);
        }
        GBAR();

        //            FI   FO  TO  WS    CLIP  RESID
        layerN< 16,  32, 2,  32, true, false>(sh + OW1, sh + OB1, sh + OBUFB + itemBase * SBUF, bufAGw, og, bp); GBAR();
        layerN< 32,  64, 4,  64, true, false>(sh + OW2, sh + OB2, bufAG,  bufBGw, og, bp); GBAR();
        layerN< 64, 128, 4, 128, true, false>(sh + OW3, sh + OB3, sh + OBUFB + itemBase * SBUF, bufAGw, og, bp); GBAR();
        layerN<128,  64, 4,  64, true, false>(sh + OW4, sh + OB4, bufAG,  bufBGw, og, bp); GBAR();
        layerN< 64,  32, 2,  32, true, false>(sh + OW5, sh + OB5, sh + OBUFB + itemBase * SBUF, bufAGw, og, bp); GBAR();
        layerN< 32,  16, 2,  16, true, false>(sh + OW6, sh + OB6, bufAG,  bufBGw, og, bp); GBAR();
        layerN< 16,   8, 2,   8, true, false>(sh + OW7, sh + OB7, sh + OBUFB + itemBase * SBUF, bufAGw, og, bp); GBAR();
        layerN<  8, 120, 4, 120, false, true>(sh + OW8, sh + OB8, bufAG,  xsGw,  og, bp); GBAR();
        // loop back: top segment needs no extra barrier
    }
    // trailing reward for t = 127
    reward16(sh, p.out, b0, itemBase, gtid, T_STEPS - 1);
}

extern "C" void kernel_launch(void* const* d_in, const int* in_sizes, int n_in,
                              void* d_out, int out_size) {
    Params p;
    p.u = (const float*)d_in[0];
    for (int i = 0; i < 9; ++i) {
        p.W[i] = (const float*)d_in[1 + 2 * i];
        p.b[i] = (const float*)d_in[2 + 2 * i];
    }
    p.Wr = (const float*)d_in[19];
    p.br = (const float*)d_in[20];
    p.out = (float*)d_out;

    cudaFuncSetAttribute(worldnet_kernel,
                         cudaFuncAttributeMaxDynamicSharedMemorySize, SMEM_BYTES);
    worldnet_kernel<<<2048 / BT, NT, SMEM_BYTES>>>(p);
}